// round 6
// baseline (speedup 1.0000x reference)
#include <cuda_runtime.h>
#include <cuda_fp16.h>
#include <cuda_pipeline.h>
#include <cstdint>

// ---------------- problem constants ----------------
#define B_SZ        8
#define L_SZ        1048576
#define KWIN        500
#define T_WIN       2097            // (L-K)/K + 1
#define TILES_PER_B 17              // ceil(2097/128)
#define GRID_MAIN   (B_SZ * TILES_PER_B)   // 136
#define NCHUNK      125             // 500 positions / 4 per chunk (K-chunk = 32)
#define OUT_DESCALE (1.0f / 16384.0f)  // C holds scaled products: 2^14 x true
#define FOLD        (1.0f / 131072.0f) // ci = 2^17 x (scaled a.b) -> C += ci * 2^-17

// smem byte offsets
#define OFF_EMBH  0u                // 257 * uint4
#define OFF_EMBR  4112u             // 257 * uint2
#define OFF_EMBQ  6168u             // 257 * uint2
#define OFF_BUF   8224u
#define SZ_AH     8192u             // [2 steps][8 mt][32 lanes][4 regs] u32
#define SZ_A8     4096u             // [8 mt][32 lanes][4 regs] u32
#define SZ_BH     16384u            // [2 steps][32 nt][32 lanes][2 regs] u32
#define SZ_B8     8192u             // [32 nt][32 lanes][2 regs] u32
#define BUF_SZ    (SZ_AH + 2*SZ_A8 + SZ_BH + 2*SZ_B8)   // 49152
#define OFF_AH(s) (OFF_BUF + (s)*BUF_SZ)
#define OFF_AL(s) (OFF_AH(s) + SZ_AH)
#define OFF_AQ(s) (OFF_AL(s) + SZ_A8)
#define OFF_BH(s) (OFF_AQ(s) + SZ_A8)
#define OFF_BQ(s) (OFF_BH(s) + SZ_BH)
#define OFF_BL(s) (OFF_BQ(s) + SZ_B8)
#define OFF_GAT   OFF_BUF           // epilogue scratch 128*260*4 = 133120
#define SMEM_ALLOC (OFF_BUF + 128u * 260u * 4u)   // 141344

// ---------------- persistent device scratch ----------------
// B operands pre-permuted into mma fragment order (per chunk blocks).
__device__ __align__(16) unsigned g_bh[125 * 4096];   // fp16 hi: per chunk [2][32][32][2] u32
__device__ __align__(16) unsigned g_bq[125 * 2048];   // s8 of B  (scale 2^-5):  [32][32][2] u32
__device__ __align__(16) unsigned g_bl[125 * 2048];   // s8 of B residual (2^-16)
__device__ __align__(16) uint4 g_embh[257];           // fp16 hi pairs e01,e23,e45,e67
__device__ __align__(16) uint2 g_embr[257];           // s8 residual (scale 2^-12), bytes e0..3 / e4..7
__device__ __align__(16) uint2 g_embq[257];           // s8 of A (scale 2^-1)
__device__ float g_pooled[B_SZ * 128];

// ---------------- helpers ----------------
__device__ __forceinline__ float wval(const float* w1, const float* w2, int o, int k) {
    const int kp = k >> 3, e = k & 7;
    const float* w = (o < 128) ? w1 : w2;
    return w[(o & 127) * 4000 + e * 500 + kp] * 128.0f;   // pre-scaled
}
__device__ __forceinline__ unsigned pack_h2(float a, float b) {
    __half h0 = __float2half_rn(a), h1 = __float2half_rn(b);
    return ((unsigned)__half_as_ushort(h1) << 16) | __half_as_ushort(h0);
}
__device__ __forceinline__ int s8q(float v) {
    int q = __float2int_rn(v);
    return q < -127 ? -127 : (q > 127 ? 127 : q);
}
__device__ __forceinline__ void hmma16816(float* c, uint4 a, uint2 b) {
    asm volatile("mma.sync.aligned.m16n8k16.row.col.f32.f16.f16.f32 "
        "{%0,%1,%2,%3}, {%4,%5,%6,%7}, {%8,%9}, {%0,%1,%2,%3};"
        : "+f"(c[0]), "+f"(c[1]), "+f"(c[2]), "+f"(c[3])
        : "r"(a.x), "r"(a.y), "r"(a.z), "r"(a.w), "r"(b.x), "r"(b.y));
}
__device__ __forceinline__ void imma16832(int* c, uint4 a, uint2 b) {
    asm volatile("mma.sync.aligned.m16n8k32.row.col.s32.s8.s8.s32 "
        "{%0,%1,%2,%3}, {%4,%5,%6,%7}, {%8,%9}, {%0,%1,%2,%3};"
        : "+r"(c[0]), "+r"(c[1]), "+r"(c[2]), "+r"(c[3])
        : "r"(a.x), "r"(a.y), "r"(a.z), "r"(a.w), "r"(b.x), "r"(b.y));
}

// ---------------- prep: fragment-order operand factories ----------------
__global__ void malconv_prep_kernel(const float* __restrict__ w1, const float* __restrict__ w2,
                                    const float* __restrict__ emb)
{
    const int bid = blockIdx.x, tid = threadIdx.x;
    if (bid < 2000) {                                   // BH: 512000 u32
        const int u = bid * 256 + tid;
        const int reg = u & 1, lane = (u >> 1) & 31, nt = (u >> 6) & 31;
        const int step = (u >> 11) & 1, ch = u >> 12;
        const int g = lane >> 2, t = lane & 3;
        const int o = nt * 8 + g;
        const int k0 = ch * 32 + step * 16 + reg * 8 + t * 2;
        g_bh[u] = pack_h2(wval(w1, w2, o, k0), wval(w1, w2, o, k0 + 1));
    } else if (bid < 3000) {                            // BQ: 256000 u32 (s8, scale 2^-5)
        const int u = (bid - 2000) * 256 + tid;
        const int reg = u & 1, lane = (u >> 1) & 31, nt = (u >> 6) & 31, ch = u >> 11;
        const int g = lane >> 2, t = lane & 3;
        const int o = nt * 8 + g;
        const int kb = ch * 32 + reg * 16 + t * 4;
        unsigned p = 0;
#pragma unroll
        for (int b = 0; b < 4; b++)
            p |= ((unsigned)(unsigned char)s8q(wval(w1, w2, o, kb + b) * 32.0f)) << (8 * b);
        g_bq[u] = p;
    } else if (bid < 4000) {                            // BL: s8 residual, scale 2^-16
        const int u = (bid - 3000) * 256 + tid;
        const int reg = u & 1, lane = (u >> 1) & 31, nt = (u >> 6) & 31, ch = u >> 11;
        const int g = lane >> 2, t = lane & 3;
        const int o = nt * 8 + g;
        const int kb = ch * 32 + reg * 16 + t * 4;
        unsigned p = 0;
#pragma unroll
        for (int b = 0; b < 4; b++) {
            const float v = wval(w1, w2, o, kb + b);
            const float r = v - __half2float(__float2half_rn(v));
            p |= ((unsigned)(unsigned char)s8q(r * 65536.0f)) << (8 * b);
        }
        g_bl[u] = p;
    } else {                                            // tables + pooled zero
        for (int v = tid; v < 257; v += 256) {
            float a[8], res[8];
            unsigned hp[4];
#pragma unroll
            for (int e = 0; e < 8; e++) {
                a[e] = emb[v * 8 + e] * 128.0f;
                res[e] = a[e] - __half2float(__float2half_rn(a[e]));
            }
#pragma unroll
            for (int q = 0; q < 4; q++) hp[q] = pack_h2(a[2 * q], a[2 * q + 1]);
            g_embh[v] = make_uint4(hp[0], hp[1], hp[2], hp[3]);
            uint2 rp, qp;
            rp.x = rp.y = qp.x = qp.y = 0;
#pragma unroll
            for (int e = 0; e < 4; e++) {
                rp.x |= ((unsigned)(unsigned char)s8q(res[e] * 4096.0f)) << (8 * e);
                rp.y |= ((unsigned)(unsigned char)s8q(res[e + 4] * 4096.0f)) << (8 * e);
                qp.x |= ((unsigned)(unsigned char)s8q(a[e] * 2.0f)) << (8 * e);
                qp.y |= ((unsigned)(unsigned char)s8q(a[e + 4] * 2.0f)) << (8 * e);
            }
            g_embr[v] = rp;
            g_embq[v] = qp;
        }
        for (int i = tid; i < B_SZ * 128; i += 256) g_pooled[i] = 0.0f;
    }
}

// ---------------- main fused conv GEMM + gate + maxpool ----------------
__global__ void __launch_bounds__(256, 1)
malconv_main_kernel(const int* __restrict__ x,
                    const float* __restrict__ b1, const float* __restrict__ b2)
{
    extern __shared__ __align__(16) char sb[];
    const int tid  = threadIdx.x;
    const int lane = tid & 31;
    const int wid  = tid >> 5;

    const int bidx = blockIdx.x / TILES_PER_B;
    const int tt   = blockIdx.x % TILES_PER_B;
    const int t0   = tt * 128;

    // tables -> smem
    uint4* embh = (uint4*)(sb + OFF_EMBH);
    uint2* embr = (uint2*)(sb + OFF_EMBR);
    uint2* embq = (uint2*)(sb + OFF_EMBQ);
    for (int i = tid; i < 257; i += 256) { embh[i] = g_embh[i]; embr[i] = g_embr[i]; embq[i] = g_embq[i]; }

    // A-fill role: 2 threads per row (h = 0/1), 2 conv positions each (p = 2h, 2h+1)
    const int arow = tid >> 1, h = tid & 1;
    int trow = t0 + arow; if (trow >= T_WIN) trow = T_WIN - 1;
    const int* xrow = x + (size_t)bidx * L_SZ + (size_t)trow * KWIN + 2 * h;

    const int mtile = arow >> 4;
    const int g     = arow & 15;
    const int glow  = g & 7, ghi = g >> 3;

    // prologue: cp.async B chunk 0 into buf 0
#pragma unroll
    for (int i = 0; i < 8; i++) {
        if (i < 4) {
            const int q = tid + i * 256;                     // 1024 16B quads (BH)
            __pipeline_memcpy_async(sb + OFF_BH(0) + q * 16, g_bh + q * 4, 16);
        } else if (i < 6) {
            const int q = tid + (i - 4) * 256;               // 512 quads (BQ)
            __pipeline_memcpy_async(sb + OFF_BQ(0) + q * 16, g_bq + q * 4, 16);
        } else {
            const int q = tid + (i - 6) * 256;               // 512 quads (BL)
            __pipeline_memcpy_async(sb + OFF_BL(0) + q * 16, g_bl + q * 4, 16);
        }
    }
    __pipeline_commit();
    int2 xv = *(const int2*)xrow;
    __syncthreads();                                         // tables ready

    // warp tiling: 8 warps = 2(M) x 4(N); warp tile 64x64
    const int wn = wid & 3, wm = wid >> 2;
    float acc[4][8][4];
#pragma unroll
    for (int a = 0; a < 4; a++)
#pragma unroll
        for (int b = 0; b < 8; b++)
#pragma unroll
            for (int j = 0; j < 4; j++) acc[a][b][j] = 0.0f;

    for (int c = 0; c < NCHUNK; ++c) {
        const int s = c & 1;
        unsigned* AHp = (unsigned*)(sb + OFF_AH(s));
        unsigned* ALp = (unsigned*)(sb + OFF_AL(s));
        unsigned* AQp = (unsigned*)(sb + OFF_AQ(s));

        // ---- fill A(c) in fragment order ----
        {
            const int2 xcur = xv;
            if (c + 1 < NCHUNK) xv = *(const int2*)(xrow + (c + 1) * 4);
#pragma unroll
            for (int i = 0; i < 2; i++) {
                const int v = i ? xcur.y : xcur.x;
                const uint4 eh = embh[v];
                const uint2 er = embr[v];
                const uint2 eq = embq[v];
                // fp16: step = h, reg = ghi + 2*i, lanes glow*4 .. +3
                {
                    const int base = ((h * 8 + mtile) * 32 + glow * 4) * 4 + (ghi + 2 * i);
                    AHp[base +  0] = eh.x;
                    AHp[base +  4] = eh.y;
                    AHp[base +  8] = eh.z;
                    AHp[base + 12] = eh.w;
                }
                // s8: reg = ghi + 2*h, lanes glow*4 + 2*i .. +1
                {
                    const int base = (mtile * 32 + glow * 4 + 2 * i) * 4 + (ghi + 2 * h);
                    ALp[base] = er.x;  ALp[base + 4] = er.y;
                    AQp[base] = eq.x;  AQp[base + 4] = eq.y;
                }
            }
        }

        __pipeline_wait_prior(0);
        __syncthreads();

        // ---- issue B(c+1) ----
        if (c + 1 < NCHUNK) {
            const int ns = s ^ 1;
            const unsigned* bh = g_bh + (size_t)(c + 1) * 4096;
            const unsigned* bq = g_bq + (size_t)(c + 1) * 2048;
            const unsigned* bl = g_bl + (size_t)(c + 1) * 2048;
#pragma unroll
            for (int i = 0; i < 8; i++) {
                if (i < 4) {
                    const int q = tid + i * 256;
                    __pipeline_memcpy_async(sb + OFF_BH(ns) + q * 16, bh + q * 4, 16);
                } else if (i < 6) {
                    const int q = tid + (i - 4) * 256;
                    __pipeline_memcpy_async(sb + OFF_BQ(ns) + q * 16, bq + q * 4, 16);
                } else {
                    const int q = tid + (i - 6) * 256;
                    __pipeline_memcpy_async(sb + OFF_BL(ns) + q * 16, bl + q * 4, 16);
                }
            }
            __pipeline_commit();
        }

        // ---- MMA on chunk c ----
        const unsigned* BHp = (const unsigned*)(sb + OFF_BH(s));
        const unsigned* BQp = (const unsigned*)(sb + OFF_BQ(s));
        const unsigned* BLp = (const unsigned*)(sb + OFF_BL(s));
#pragma unroll
        for (int mt = 0; mt < 4; mt++) {
            const int MT = wm * 4 + mt;
            const uint4 ah0 = *(const uint4*)(AHp + ((0 + MT) * 32 + lane) * 4);
            const uint4 ah1 = *(const uint4*)(AHp + ((8 + MT) * 32 + lane) * 4);
            const uint4 alv = *(const uint4*)(ALp + (MT * 32 + lane) * 4);
            const uint4 aqv = *(const uint4*)(AQp + (MT * 32 + lane) * 4);
#pragma unroll
            for (int nt = 0; nt < 8; nt++) {
                const int NT = wn * 8 + nt;
                const uint2 bh0 = *(const uint2*)(BHp + ((0  + NT) * 32 + lane) * 2);
                const uint2 bh1 = *(const uint2*)(BHp + ((32 + NT) * 32 + lane) * 2);
                const uint2 bqv = *(const uint2*)(BQp + (NT * 32 + lane) * 2);
                const uint2 blv = *(const uint2*)(BLp + (NT * 32 + lane) * 2);
                float* C = acc[mt][nt];
                hmma16816(C, ah0, bh0);
                hmma16816(C, ah1, bh1);
                int ci[4] = {0, 0, 0, 0};
                imma16832(ci, alv, bqv);     // Al * B_q8   (units 2^-12 * 2^-5 = 2^-17)
                imma16832(ci, aqv, blv);     // A_q8 * Bl   (units 2^-1  * 2^-16 = 2^-17)
                C[0] += FOLD * (float)ci[0];
                C[1] += FOLD * (float)ci[1];
                C[2] += FOLD * (float)ci[2];
                C[3] += FOLD * (float)ci[3];
            }
        }
    }

    // ---- epilogue ----
    __syncthreads();
    float* gat = (float*)(sb + OFF_GAT);                 // [row][o], stride 260
    const int grp = lane >> 2, tig = lane & 3;
#pragma unroll
    for (int mt = 0; mt < 4; mt++)
#pragma unroll
        for (int nt = 0; nt < 8; nt++)
#pragma unroll
            for (int j = 0; j < 4; j++) {
                const int row = wm * 64 + mt * 16 + grp + 8 * (j >> 1);
                const int col = wn * 64 + nt * 8 + 2 * tig + (j & 1);
                gat[row * 260 + col] = acc[mt][nt][j];
            }
    __syncthreads();

    {
        const int o = tid & 127;
        const int half = tid >> 7;
        const float b1v = b1[o], b2v = b2[o];
        int rend = T_WIN - t0; if (rend > 128) rend = 128;
        const int r0 = half * 64;
        int r1 = r0 + 64; if (r1 > rend) r1 = rend;
        float m = 0.0f;
        for (int r = r0; r < r1; r++) {
            const float c1 = gat[r * 260 + o]       * OUT_DESCALE + b1v;
            const float c2 = gat[r * 260 + o + 128] * OUT_DESCALE + b2v;
            const float gg = fmaxf(c1, 0.0f) * (1.0f / (1.0f + __expf(-c2)));
            m = fmaxf(m, gg);
        }
        atomicMax((int*)(g_pooled + bidx * 128 + o), __float_as_int(m));  // m >= 0
    }
}

// ---------------- dense head ----------------
__global__ void malconv_head_kernel(const float* __restrict__ wd1, const float* __restrict__ bd1,
                                    const float* __restrict__ wd2, const float* __restrict__ bd2,
                                    float* __restrict__ out)
{
    __shared__ float psh[B_SZ * 128];
    __shared__ float hsh[B_SZ * 128];
    const int tid = threadIdx.x;                   // 1024 threads
    psh[tid] = g_pooled[tid];
    __syncthreads();
    const int b = tid >> 7, j = tid & 127;
    float acc = bd1[j];
    const float* wr = wd1 + j * 128;
#pragma unroll 8
    for (int o = 0; o < 128; o++) acc += psh[b * 128 + o] * wr[o];
    hsh[tid] = fmaxf(acc, 0.0f);
    __syncthreads();
    if (tid < B_SZ) {
        float a2 = bd2[0];
#pragma unroll 8
        for (int jj = 0; jj < 128; jj++) a2 += hsh[tid * 128 + jj] * wd2[jj];
        out[tid] = 1.0f / (1.0f + __expf(-a2));
    }
}

// ---------------- launch ----------------
extern "C" void kernel_launch(void* const* d_in, const int* in_sizes, int n_in,
                              void* d_out, int out_size) {
    (void)in_sizes; (void)n_in; (void)out_size;
    const int*   x   = (const int*)d_in[0];
    const float* emb = (const float*)d_in[1];
    const float* w1  = (const float*)d_in[2];
    const float* b1  = (const float*)d_in[3];
    const float* w2  = (const float*)d_in[4];
    const float* b2  = (const float*)d_in[5];
    const float* wd1 = (const float*)d_in[6];
    const float* bd1 = (const float*)d_in[7];
    const float* wd2 = (const float*)d_in[8];
    const float* bd2 = (const float*)d_in[9];
    float* out = (float*)d_out;

    cudaFuncSetAttribute(malconv_main_kernel,
                         cudaFuncAttributeMaxDynamicSharedMemorySize, (int)SMEM_ALLOC);

    malconv_prep_kernel<<<4001, 256>>>(w1, w2, emb);
    malconv_main_kernel<<<GRID_MAIN, 256, SMEM_ALLOC>>>(x, b1, b2);
    malconv_head_kernel<<<1, 1024>>>(wd1, bd1, wd2, bd2, out);
}

// round 7
// speedup vs baseline: 1.9541x; 1.9541x over previous
#include <cuda_runtime.h>
#include <cuda_fp16.h>
#include <cuda_fp8.h>
#include <cuda_pipeline.h>
#include <cstdint>

// ---------------- problem constants ----------------
#define B_SZ        8
#define L_SZ        1048576
#define KWIN        500
#define T_WIN       2097            // (L-K)/K + 1
#define TILES_PER_B 17              // ceil(2097/128)
#define GRID_MAIN   (B_SZ * TILES_PER_B)   // 136
#define NCHUNK      125             // 500 positions / 4 per chunk (K-chunk = 32)
#define OUT_DESCALE (1.0f / 16384.0f)  // C holds scaled products: 2^14 x true

// smem byte offsets
#define OFF_EMBH   0u               // 257 * uint4 (fp16 hi pairs)
#define OFF_EMBR8  4112u            // 257 * uint2 (e4m3 residual * 2^5)
#define OFF_BUF    6176u
#define SZ_AH      8192u            // [2 steps][8 mt][32 lanes][4 regs] u32 (fp16 k16 A frags)
#define SZ_AL8     4096u            // [8 mt][32 lanes][4 regs] u32 (e4m3 k32 A frags)
#define SZ_BH      16384u           // [2 steps][32 nt][32 lanes][2 regs] u32 (fp16 k16 B frags)
#define SZ_BL      16384u           // same, residual fp16
#define SZ_BH8     8192u            // [32 nt][32 lanes][2 regs] u32 (e4m3 k32 B frags)
#define BUF_SZ     (SZ_AH + SZ_AL8 + SZ_BH + SZ_BL + SZ_BH8)   // 53248
#define OFF_AH(s)  (OFF_BUF + (s)*BUF_SZ)
#define OFF_AL8(s) (OFF_AH(s) + SZ_AH)
#define OFF_BH(s)  (OFF_AL8(s) + SZ_AL8)
#define OFF_BL(s)  (OFF_BH(s) + SZ_BH)
#define OFF_BH8(s) (OFF_BL(s) + SZ_BL)
#define OFF_GAT    OFF_BUF          // epilogue scratch 128*260*4 = 133120
#define SMEM_ALLOC (OFF_BUF + 128u * 260u * 4u)   // 139296

// ---------------- persistent device scratch ----------------
__device__ __align__(16) unsigned g_bh[125 * 4096];   // fp16 hi, k16 frag order
__device__ __align__(16) unsigned g_bl[125 * 4096];   // fp16 residual, k16 frag order
__device__ __align__(16) unsigned g_bh8[125 * 2048];  // e4m3(bh * 2^-5), k32 frag order
__device__ __align__(16) uint4 g_embh[257];           // fp16 hi pairs e01,e23,e45,e67
__device__ __align__(16) uint2 g_embr8[257];          // e4m3(al * 2^5), bytes e0..3 / e4..7
__device__ float g_pooled[B_SZ * 128];

// ---------------- helpers ----------------
__device__ __forceinline__ float wval(const float* w1, const float* w2, int o, int k) {
    const int kp = k >> 3, e = k & 7;
    const float* w = (o < 128) ? w1 : w2;
    return w[(o & 127) * 4000 + e * 500 + kp] * 128.0f;   // pre-scaled by 2^7
}
__device__ __forceinline__ unsigned pack_h2(float a, float b) {
    __half h0 = __float2half_rn(a), h1 = __float2half_rn(b);
    return ((unsigned)__half_as_ushort(h1) << 16) | __half_as_ushort(h0);
}
__device__ __forceinline__ unsigned char f8(float v) {
    __nv_fp8_e4m3 t(v);
    return *reinterpret_cast<unsigned char*>(&t);
}
__device__ __forceinline__ void hmma16816(float* c, uint4 a, uint2 b) {
    asm volatile("mma.sync.aligned.m16n8k16.row.col.f32.f16.f16.f32 "
        "{%0,%1,%2,%3}, {%4,%5,%6,%7}, {%8,%9}, {%0,%1,%2,%3};"
        : "+f"(c[0]), "+f"(c[1]), "+f"(c[2]), "+f"(c[3])
        : "r"(a.x), "r"(a.y), "r"(a.z), "r"(a.w), "r"(b.x), "r"(b.y));
}
__device__ __forceinline__ void qmma16832(float* c, uint4 a, uint2 b) {
    asm volatile("mma.sync.aligned.m16n8k32.row.col.f32.e4m3.e4m3.f32 "
        "{%0,%1,%2,%3}, {%4,%5,%6,%7}, {%8,%9}, {%0,%1,%2,%3};"
        : "+f"(c[0]), "+f"(c[1]), "+f"(c[2]), "+f"(c[3])
        : "r"(a.x), "r"(a.y), "r"(a.z), "r"(a.w), "r"(b.x), "r"(b.y));
}

// ---------------- prep: fragment-order operand factories ----------------
__global__ void malconv_prep_kernel(const float* __restrict__ w1, const float* __restrict__ w2,
                                    const float* __restrict__ emb)
{
    const int bid = blockIdx.x, tid = threadIdx.x;
    if (bid < 2000) {                                   // BH: 512000 u32, k16 frag order
        const int u = bid * 256 + tid;
        const int reg = u & 1, lane = (u >> 1) & 31, nt = (u >> 6) & 31;
        const int step = (u >> 11) & 1, ch = u >> 12;
        const int g = lane >> 2, t = lane & 3;
        const int o = nt * 8 + g;
        const int k0 = ch * 32 + step * 16 + reg * 8 + t * 2;
        g_bh[u] = pack_h2(wval(w1, w2, o, k0), wval(w1, w2, o, k0 + 1));
    } else if (bid < 4000) {                            // BL: fp16 residual, k16 frag order
        const int u = (bid - 2000) * 256 + tid;
        const int reg = u & 1, lane = (u >> 1) & 31, nt = (u >> 6) & 31;
        const int step = (u >> 11) & 1, ch = u >> 12;
        const int g = lane >> 2, t = lane & 3;
        const int o = nt * 8 + g;
        const int k0 = ch * 32 + step * 16 + reg * 8 + t * 2;
        const float v0 = wval(w1, w2, o, k0), v1 = wval(w1, w2, o, k0 + 1);
        const float r0 = v0 - __half2float(__float2half_rn(v0));
        const float r1 = v1 - __half2float(__float2half_rn(v1));
        g_bl[u] = pack_h2(r0, r1);
    } else if (bid < 5000) {                            // BH8: e4m3(bh * 2^-5), k32 frag order
        const int u = (bid - 4000) * 256 + tid;
        const int reg = u & 1, lane = (u >> 1) & 31, nt = (u >> 6) & 31, ch = u >> 11;
        const int g = lane >> 2, t = lane & 3;
        const int o = nt * 8 + g;
        const int kb = ch * 32 + reg * 16 + t * 4;
        unsigned p = 0;
#pragma unroll
        for (int b = 0; b < 4; b++) {
            const float v = wval(w1, w2, o, kb + b);
            const float bh = __half2float(__float2half_rn(v));
            p |= ((unsigned)f8(bh * 0.03125f)) << (8 * b);
        }
        g_bh8[u] = p;
    } else {                                            // tables + pooled zero
        for (int v = tid; v < 257; v += 256) {
            float a[8], al[8];
            unsigned hp[4];
#pragma unroll
            for (int e = 0; e < 8; e++) {
                a[e] = emb[v * 8 + e] * 128.0f;
                al[e] = a[e] - __half2float(__float2half_rn(a[e]));
            }
#pragma unroll
            for (int q = 0; q < 4; q++) hp[q] = pack_h2(a[2 * q], a[2 * q + 1]);
            g_embh[v] = make_uint4(hp[0], hp[1], hp[2], hp[3]);
            uint2 rp; rp.x = rp.y = 0;
#pragma unroll
            for (int e = 0; e < 4; e++) {
                rp.x |= ((unsigned)f8(al[e]     * 32.0f)) << (8 * e);
                rp.y |= ((unsigned)f8(al[e + 4] * 32.0f)) << (8 * e);
            }
            g_embr8[v] = rp;
        }
        for (int i = tid; i < B_SZ * 128; i += 256) g_pooled[i] = 0.0f;
    }
}

// ---------------- main fused conv GEMM + gate + maxpool ----------------
__global__ void __launch_bounds__(256, 1)
malconv_main_kernel(const int* __restrict__ x,
                    const float* __restrict__ b1, const float* __restrict__ b2)
{
    extern __shared__ __align__(16) char sb[];
    const int tid  = threadIdx.x;
    const int lane = tid & 31;
    const int wid  = tid >> 5;

    const int bidx = blockIdx.x / TILES_PER_B;
    const int tt   = blockIdx.x % TILES_PER_B;
    const int t0   = tt * 128;

    // tables -> smem
    uint4* embh  = (uint4*)(sb + OFF_EMBH);
    uint2* embr8 = (uint2*)(sb + OFF_EMBR8);
    for (int i = tid; i < 257; i += 256) { embh[i] = g_embh[i]; embr8[i] = g_embr8[i]; }

    // A-fill role: 2 threads per row (h = 0/1), 2 conv positions each (p = 2h, 2h+1)
    const int arow = tid >> 1, h = tid & 1;
    int trow = t0 + arow; if (trow >= T_WIN) trow = T_WIN - 1;
    const int* xrow = x + (size_t)bidx * L_SZ + (size_t)trow * KWIN + 2 * h;

    const int mtile = arow >> 4;
    const int g     = arow & 15;
    const int glow  = g & 7, ghi = g >> 3;

    // prologue: cp.async B chunk 0 into buf 0 (BH 1024 quads, BL 1024, BH8 512)
#pragma unroll
    for (int i = 0; i < 10; i++) {
        if (i < 4) {
            const int q = tid + i * 256;
            __pipeline_memcpy_async(sb + OFF_BH(0) + q * 16, g_bh + q * 4, 16);
        } else if (i < 8) {
            const int q = tid + (i - 4) * 256;
            __pipeline_memcpy_async(sb + OFF_BL(0) + q * 16, g_bl + q * 4, 16);
        } else {
            const int q = tid + (i - 8) * 256;
            __pipeline_memcpy_async(sb + OFF_BH8(0) + q * 16, g_bh8 + q * 4, 16);
        }
    }
    __pipeline_commit();
    int2 xv = *(const int2*)xrow;
    __syncthreads();                                         // tables ready

    // warp tiling: 8 warps = 2(M) x 4(N); warp tile 64x64
    const int wn = wid & 3, wm = wid >> 2;
    float acc[4][8][4];
#pragma unroll
    for (int a = 0; a < 4; a++)
#pragma unroll
        for (int b = 0; b < 8; b++)
#pragma unroll
            for (int j = 0; j < 4; j++) acc[a][b][j] = 0.0f;

    for (int c = 0; c < NCHUNK; ++c) {
        const int s = c & 1;
        unsigned* AHp  = (unsigned*)(sb + OFF_AH(s));
        unsigned* AL8p = (unsigned*)(sb + OFF_AL8(s));

        // ---- fill A(c) in fragment order ----
        {
            const int2 xcur = xv;
            if (c + 1 < NCHUNK) xv = *(const int2*)(xrow + (c + 1) * 4);
#pragma unroll
            for (int i = 0; i < 2; i++) {
                const int v = i ? xcur.y : xcur.x;
                const uint4 eh = embh[v];
                const uint2 er = embr8[v];
                // fp16 k16 frags: step = h, reg = ghi + 2*i, lanes glow*4 .. +3
                {
                    const int base = ((h * 8 + mtile) * 32 + glow * 4) * 4 + (ghi + 2 * i);
                    AHp[base +  0] = eh.x;
                    AHp[base +  4] = eh.y;
                    AHp[base +  8] = eh.z;
                    AHp[base + 12] = eh.w;
                }
                // e4m3 k32 frags: reg = ghi + 2*h, lanes glow*4 + 2*i .. +1
                {
                    const int base = (mtile * 32 + glow * 4 + 2 * i) * 4 + (ghi + 2 * h);
                    AL8p[base] = er.x;  AL8p[base + 4] = er.y;
                }
            }
        }

        __pipeline_wait_prior(0);
        __syncthreads();

        // ---- issue B(c+1) ----
        if (c + 1 < NCHUNK) {
            const int ns = s ^ 1;
            const unsigned* bh  = g_bh  + (size_t)(c + 1) * 4096;
            const unsigned* bl  = g_bl  + (size_t)(c + 1) * 4096;
            const unsigned* bh8 = g_bh8 + (size_t)(c + 1) * 2048;
#pragma unroll
            for (int i = 0; i < 10; i++) {
                if (i < 4) {
                    const int q = tid + i * 256;
                    __pipeline_memcpy_async(sb + OFF_BH(ns) + q * 16, bh + q * 4, 16);
                } else if (i < 8) {
                    const int q = tid + (i - 4) * 256;
                    __pipeline_memcpy_async(sb + OFF_BL(ns) + q * 16, bl + q * 4, 16);
                } else {
                    const int q = tid + (i - 8) * 256;
                    __pipeline_memcpy_async(sb + OFF_BH8(ns) + q * 16, bh8 + q * 4, 16);
                }
            }
            __pipeline_commit();
        }

        // ---- MMA on chunk c: 4 HMMA + 1 QMMA per 16x8 subtile ----
        const unsigned* BHp  = (const unsigned*)(sb + OFF_BH(s));
        const unsigned* BLp  = (const unsigned*)(sb + OFF_BL(s));
        const unsigned* BH8p = (const unsigned*)(sb + OFF_BH8(s));
#pragma unroll
        for (int mt = 0; mt < 4; mt++) {
            const int MT = wm * 4 + mt;
            const uint4 ah0 = *(const uint4*)(AHp  + ((0 + MT) * 32 + lane) * 4);
            const uint4 ah1 = *(const uint4*)(AHp  + ((8 + MT) * 32 + lane) * 4);
            const uint4 al8 = *(const uint4*)(AL8p + (MT * 32 + lane) * 4);
#pragma unroll
            for (int nt = 0; nt < 8; nt++) {
                const int NT = wn * 8 + nt;
                const uint2 bh0 = *(const uint2*)(BHp  + ((0  + NT) * 32 + lane) * 2);
                const uint2 bh1 = *(const uint2*)(BHp  + ((32 + NT) * 32 + lane) * 2);
                const uint2 bl0 = *(const uint2*)(BLp  + ((0  + NT) * 32 + lane) * 2);
                const uint2 bl1 = *(const uint2*)(BLp  + ((32 + NT) * 32 + lane) * 2);
                const uint2 b8  = *(const uint2*)(BH8p + (NT * 32 + lane) * 2);
                float* C = acc[mt][nt];
                hmma16816(C, ah0, bh0);      // Ah * Bh (k steps 0,1)
                hmma16816(C, ah1, bh1);
                hmma16816(C, ah0, bl0);      // Ah * Bl
                hmma16816(C, ah1, bl1);
                qmma16832(C, al8, b8);       // Al * Bh via fp8 (scales 2^5 * 2^-5 = 1)
            }
        }
    }

    // ---- epilogue ----
    __syncthreads();
    float* gat = (float*)(sb + OFF_GAT);                 // [row][o], stride 260
    const int grp = lane >> 2, tig = lane & 3;
#pragma unroll
    for (int mt = 0; mt < 4; mt++)
#pragma unroll
        for (int nt = 0; nt < 8; nt++)
#pragma unroll
            for (int j = 0; j < 4; j++) {
                const int row = wm * 64 + mt * 16 + grp + 8 * (j >> 1);
                const int col = wn * 64 + nt * 8 + 2 * tig + (j & 1);
                gat[row * 260 + col] = acc[mt][nt][j];
            }
    __syncthreads();

    {
        const int o = tid & 127;
        const int half = tid >> 7;
        const float b1v = b1[o], b2v = b2[o];
        int rend = T_WIN - t0; if (rend > 128) rend = 128;
        const int r0 = half * 64;
        int r1 = r0 + 64; if (r1 > rend) r1 = rend;
        float m = 0.0f;
        for (int r = r0; r < r1; r++) {
            const float c1 = gat[r * 260 + o]       * OUT_DESCALE + b1v;
            const float c2 = gat[r * 260 + o + 128] * OUT_DESCALE + b2v;
            const float gg = fmaxf(c1, 0.0f) * (1.0f / (1.0f + __expf(-c2)));
            m = fmaxf(m, gg);
        }
        atomicMax((int*)(g_pooled + bidx * 128 + o), __float_as_int(m));  // m >= 0
    }
}

// ---------------- dense head ----------------
__global__ void malconv_head_kernel(const float* __restrict__ wd1, const float* __restrict__ bd1,
                                    const float* __restrict__ wd2, const float* __restrict__ bd2,
                                    float* __restrict__ out)
{
    __shared__ float psh[B_SZ * 128];
    __shared__ float hsh[B_SZ * 128];
    const int tid = threadIdx.x;                   // 1024 threads
    psh[tid] = g_pooled[tid];
    __syncthreads();
    const int b = tid >> 7, j = tid & 127;
    float acc = bd1[j];
    const float* wr = wd1 + j * 128;
#pragma unroll 8
    for (int o = 0; o < 128; o++) acc += psh[b * 128 + o] * wr[o];
    hsh[tid] = fmaxf(acc, 0.0f);
    __syncthreads();
    if (tid < B_SZ) {
        float a2 = bd2[0];
#pragma unroll 8
        for (int jj = 0; jj < 128; jj++) a2 += hsh[tid * 128 + jj] * wd2[jj];
        out[tid] = 1.0f / (1.0f + __expf(-a2));
    }
}

// ---------------- launch ----------------
extern "C" void kernel_launch(void* const* d_in, const int* in_sizes, int n_in,
                              void* d_out, int out_size) {
    (void)in_sizes; (void)n_in; (void)out_size;
    const int*   x   = (const int*)d_in[0];
    const float* emb = (const float*)d_in[1];
    const float* w1  = (const float*)d_in[2];
    const float* b1  = (const float*)d_in[3];
    const float* w2  = (const float*)d_in[4];
    const float* b2  = (const float*)d_in[5];
    const float* wd1 = (const float*)d_in[6];
    const float* bd1 = (const float*)d_in[7];
    const float* wd2 = (const float*)d_in[8];
    const float* bd2 = (const float*)d_in[9];
    float* out = (float*)d_out;

    cudaFuncSetAttribute(malconv_main_kernel,
                         cudaFuncAttributeMaxDynamicSharedMemorySize, (int)SMEM_ALLOC);

    malconv_prep_kernel<<<5001, 256>>>(w1, w2, emb);
    malconv_main_kernel<<<GRID_MAIN, 256, SMEM_ALLOC>>>(x, b1, b2);
    malconv_head_kernel<<<1, 1024>>>(wd1, bd1, wd2, bd2, out);
}

// round 8
// speedup vs baseline: 2.5268x; 1.2930x over previous
#include <cuda_runtime.h>
#include <cuda_fp16.h>
#include <cuda_pipeline.h>
#include <cstdint>

// ---------------- problem constants ----------------
#define B_SZ        8
#define L_SZ        1048576
#define KWIN        500
#define T_WIN       2097            // (L-K)/K + 1
#define TILES_PER_B 17              // ceil(2097/128)
#define GRID_MAIN   (B_SZ * TILES_PER_B)   // 136
#define NCHUNK      125             // 500 positions / 4 per chunk (K-chunk = 32)
#define OUT_DESCALE (1.0f / 16384.0f)  // C holds scaled products: 2^14 x true

// 2-term compensated fp16: C = Ah*R + P*Q
//   R = fl16(31/32 * B), rB = 31/32*B - R, Q = fl16(B/32 + rB)
//   Ah = fl16(A),        P  = fl16(Ah + 32*(A - Ah))
// => A-coefficient of B is exact; corrections enter at 2^-16 operand-equiv.

// smem byte offsets
#define OFF_EMBH   0u               // 257 * uint4 (fp16 Ah pairs)
#define OFF_EMBP   4112u            // 257 * uint4 (fp16 P pairs)
#define OFF_BUF    8224u
#define SZ_AH      8192u            // [2 steps][8 mt][32 lanes][4 regs] u32
#define SZ_AP      8192u
#define SZ_BR      16384u           // [2 steps][32 nt][32 lanes][2 regs] u32
#define SZ_BQ      16384u
#define BUF_SZ     (SZ_AH + SZ_AP + SZ_BR + SZ_BQ)   // 49152
#define OFF_AH(s)  (OFF_BUF + (s)*BUF_SZ)
#define OFF_AP(s)  (OFF_AH(s) + SZ_AH)
#define OFF_BR(s)  (OFF_AP(s) + SZ_AP)
#define OFF_BQ(s)  (OFF_BR(s) + SZ_BR)
#define OFF_GAT    OFF_BUF          // epilogue scratch 128*260*4 = 133120
#define SMEM_ALLOC (OFF_BUF + 128u * 260u * 4u)   // 141344

// ---------------- persistent device scratch ----------------
__device__ __align__(16) unsigned g_br[125 * 4096];   // R frags, k16 frag order per chunk
__device__ __align__(16) unsigned g_bq[125 * 4096];   // Q frags, k16 frag order per chunk
__device__ __align__(16) uint4 g_embh[257];           // Ah pairs e01,e23,e45,e67
__device__ __align__(16) uint4 g_embp[257];           // P  pairs
__device__ float g_pooled[B_SZ * 128];

// ---------------- helpers ----------------
__device__ __forceinline__ float wval(const float* w1, const float* w2, int o, int k) {
    const int kp = k >> 3, e = k & 7;
    const float* w = (o < 128) ? w1 : w2;
    return w[(o & 127) * 4000 + e * 500 + kp] * 128.0f;   // pre-scaled by 2^7
}
__device__ __forceinline__ unsigned pack_h2(float a, float b) {
    __half h0 = __float2half_rn(a), h1 = __float2half_rn(b);
    return ((unsigned)__half_as_ushort(h1) << 16) | __half_as_ushort(h0);
}
__device__ __forceinline__ float bRval(float v) {          // fl16(31/32 v) as float
    return __half2float(__float2half_rn(v * 0.96875f));
}
__device__ __forceinline__ float bQval(float v) {          // B/32 + residual of R
    const float rB = v * 0.96875f - bRval(v);
    return v * 0.03125f + rB;                              // rounded once in pack_h2
}
__device__ __forceinline__ void hmma16816(float* c, uint4 a, uint2 b) {
    asm volatile("mma.sync.aligned.m16n8k16.row.col.f32.f16.f16.f32 "
        "{%0,%1,%2,%3}, {%4,%5,%6,%7}, {%8,%9}, {%0,%1,%2,%3};"
        : "+f"(c[0]), "+f"(c[1]), "+f"(c[2]), "+f"(c[3])
        : "r"(a.x), "r"(a.y), "r"(a.z), "r"(a.w), "r"(b.x), "r"(b.y));
}

// ---------------- prep: fragment-order operand factories ----------------
__global__ void malconv_prep_kernel(const float* __restrict__ w1, const float* __restrict__ w2,
                                    const float* __restrict__ emb)
{
    const int bid = blockIdx.x, tid = threadIdx.x;
    if (bid < 4000) {                                   // BR/BQ: 512000 u32 each, k16 frag order
        const bool isR = bid < 2000;
        const int u = (isR ? bid : bid - 2000) * 256 + tid;
        const int reg = u & 1, lane = (u >> 1) & 31, nt = (u >> 6) & 31;
        const int step = (u >> 11) & 1, ch = u >> 12;
        const int g = lane >> 2, t = lane & 3;
        const int o = nt * 8 + g;
        const int k0 = ch * 32 + step * 16 + reg * 8 + t * 2;
        const float v0 = wval(w1, w2, o, k0), v1 = wval(w1, w2, o, k0 + 1);
        if (isR) g_br[u] = pack_h2(bRval(v0), bRval(v1));
        else     g_bq[u] = pack_h2(bQval(v0), bQval(v1));
    } else {                                            // emb tables + pooled zero
        for (int v = tid; v < 257; v += 256) {
            float a[8], ah[8], p[8];
            unsigned hp[4], pp[4];
#pragma unroll
            for (int e = 0; e < 8; e++) {
                a[e]  = emb[v * 8 + e] * 128.0f;
                ah[e] = __half2float(__float2half_rn(a[e]));
                p[e]  = ah[e] + 32.0f * (a[e] - ah[e]);
            }
#pragma unroll
            for (int q = 0; q < 4; q++) {
                hp[q] = pack_h2(ah[2 * q], ah[2 * q + 1]);
                pp[q] = pack_h2(p[2 * q],  p[2 * q + 1]);
            }
            g_embh[v] = make_uint4(hp[0], hp[1], hp[2], hp[3]);
            g_embp[v] = make_uint4(pp[0], pp[1], pp[2], pp[3]);
        }
        for (int i = tid; i < B_SZ * 128; i += 256) g_pooled[i] = 0.0f;
    }
}

// ---------------- main fused conv GEMM + gate + maxpool ----------------
__global__ void __launch_bounds__(256, 1)
malconv_main_kernel(const int* __restrict__ x,
                    const float* __restrict__ b1, const float* __restrict__ b2)
{
    extern __shared__ __align__(16) char sb[];
    const int tid  = threadIdx.x;
    const int lane = tid & 31;
    const int wid  = tid >> 5;

    const int bidx = blockIdx.x / TILES_PER_B;
    const int tt   = blockIdx.x % TILES_PER_B;
    const int t0   = tt * 128;

    // tables -> smem
    uint4* embh = (uint4*)(sb + OFF_EMBH);
    uint4* embp = (uint4*)(sb + OFF_EMBP);
    for (int i = tid; i < 257; i += 256) { embh[i] = g_embh[i]; embp[i] = g_embp[i]; }

    // A-fill role: 2 threads per row (h = 0/1), 2 conv positions each (p = 2h, 2h+1)
    const int arow = tid >> 1, h = tid & 1;
    int trow = t0 + arow; if (trow >= T_WIN) trow = T_WIN - 1;
    const int* xrow = x + (size_t)bidx * L_SZ + (size_t)trow * KWIN + 2 * h;

    const int mtile = arow >> 4;
    const int g     = arow & 15;
    const int glow  = g & 7, ghi = g >> 3;

    // prologue: cp.async B chunk 0 into buf 0 (BR 1024 quads, BQ 1024 quads)
#pragma unroll
    for (int i = 0; i < 8; i++) {
        if (i < 4) {
            const int q = tid + i * 256;
            __pipeline_memcpy_async(sb + OFF_BR(0) + q * 16, g_br + q * 4, 16);
        } else {
            const int q = tid + (i - 4) * 256;
            __pipeline_memcpy_async(sb + OFF_BQ(0) + q * 16, g_bq + q * 4, 16);
        }
    }
    __pipeline_commit();
    int2 xv = *(const int2*)xrow;
    __syncthreads();                                         // tables ready

    // warp tiling: 8 warps = 2(M) x 4(N); warp tile 64x64
    const int wn = wid & 3, wm = wid >> 2;
    float acc[4][8][4];
#pragma unroll
    for (int a = 0; a < 4; a++)
#pragma unroll
        for (int b = 0; b < 8; b++)
#pragma unroll
            for (int j = 0; j < 4; j++) acc[a][b][j] = 0.0f;

    for (int c = 0; c < NCHUNK; ++c) {
        const int s = c & 1;
        unsigned* AHp = (unsigned*)(sb + OFF_AH(s));
        unsigned* APp = (unsigned*)(sb + OFF_AP(s));

        // ---- fill A(c) in k16 fragment order (Ah and P streams) ----
        {
            const int2 xcur = xv;
            if (c + 1 < NCHUNK) xv = *(const int2*)(xrow + (c + 1) * 4);
#pragma unroll
            for (int i = 0; i < 2; i++) {
                const int v = i ? xcur.y : xcur.x;
                const uint4 eh = embh[v];
                const uint4 ep = embp[v];
                // step = h, reg = ghi + 2*i, lanes glow*4 .. +3
                const int base = ((h * 8 + mtile) * 32 + glow * 4) * 4 + (ghi + 2 * i);
                AHp[base +  0] = eh.x;
                AHp[base +  4] = eh.y;
                AHp[base +  8] = eh.z;
                AHp[base + 12] = eh.w;
                APp[base +  0] = ep.x;
                APp[base +  4] = ep.y;
                APp[base +  8] = ep.z;
                APp[base + 12] = ep.w;
            }
        }

        __pipeline_wait_prior(0);
        __syncthreads();

        // ---- issue B(c+1) ----
        if (c + 1 < NCHUNK) {
            const int ns = s ^ 1;
            const unsigned* br = g_br + (size_t)(c + 1) * 4096;
            const unsigned* bq = g_bq + (size_t)(c + 1) * 4096;
#pragma unroll
            for (int i = 0; i < 8; i++) {
                if (i < 4) {
                    const int q = tid + i * 256;
                    __pipeline_memcpy_async(sb + OFF_BR(ns) + q * 16, br + q * 4, 16);
                } else {
                    const int q = tid + (i - 4) * 256;
                    __pipeline_memcpy_async(sb + OFF_BQ(ns) + q * 16, bq + q * 4, 16);
                }
            }
            __pipeline_commit();
        }

        // ---- MMA on chunk c: 4 HMMA per 16x8 subtile (2 main + 2 correction) ----
        const unsigned* BRp = (const unsigned*)(sb + OFF_BR(s));
        const unsigned* BQp = (const unsigned*)(sb + OFF_BQ(s));
#pragma unroll
        for (int mt = 0; mt < 4; mt++) {
            const int MT = wm * 4 + mt;
            const uint4 ah0 = *(const uint4*)(AHp + ((0 + MT) * 32 + lane) * 4);
            const uint4 ah1 = *(const uint4*)(AHp + ((8 + MT) * 32 + lane) * 4);
            const uint4 ap0 = *(const uint4*)(APp + ((0 + MT) * 32 + lane) * 4);
            const uint4 ap1 = *(const uint4*)(APp + ((8 + MT) * 32 + lane) * 4);
#pragma unroll
            for (int nt = 0; nt < 8; nt++) {
                const int NT = wn * 8 + nt;
                const uint2 br0 = *(const uint2*)(BRp + ((0  + NT) * 32 + lane) * 2);
                const uint2 br1 = *(const uint2*)(BRp + ((32 + NT) * 32 + lane) * 2);
                const uint2 bq0 = *(const uint2*)(BQp + ((0  + NT) * 32 + lane) * 2);
                const uint2 bq1 = *(const uint2*)(BQp + ((32 + NT) * 32 + lane) * 2);
                float* C = acc[mt][nt];
                hmma16816(C, ah0, br0);      // Ah * R   (k steps 0,1)
                hmma16816(C, ah1, br1);
                hmma16816(C, ap0, bq0);      // P * Q
                hmma16816(C, ap1, bq1);
            }
        }
    }

    // ---- epilogue ----
    __syncthreads();
    float* gat = (float*)(sb + OFF_GAT);                 // [row][o], stride 260
    const int grp = lane >> 2, tig = lane & 3;
#pragma unroll
    for (int mt = 0; mt < 4; mt++)
#pragma unroll
        for (int nt = 0; nt < 8; nt++)
#pragma unroll
            for (int j = 0; j < 4; j++) {
                const int row = wm * 64 + mt * 16 + grp + 8 * (j >> 1);
                const int col = wn * 64 + nt * 8 + 2 * tig + (j & 1);
                gat[row * 260 + col] = acc[mt][nt][j];
            }
    __syncthreads();

    {
        const int o = tid & 127;
        const int half = tid >> 7;
        const float b1v = b1[o], b2v = b2[o];
        int rend = T_WIN - t0; if (rend > 128) rend = 128;
        const int r0 = half * 64;
        int r1 = r0 + 64; if (r1 > rend) r1 = rend;
        float m = 0.0f;
        for (int r = r0; r < r1; r++) {
            const float c1 = gat[r * 260 + o]       * OUT_DESCALE + b1v;
            const float c2 = gat[r * 260 + o + 128] * OUT_DESCALE + b2v;
            const float gg = fmaxf(c1, 0.0f) * (1.0f / (1.0f + __expf(-c2)));
            m = fmaxf(m, gg);
        }
        atomicMax((int*)(g_pooled + bidx * 128 + o), __float_as_int(m));  // m >= 0
    }
}

// ---------------- dense head ----------------
__global__ void malconv_head_kernel(const float* __restrict__ wd1, const float* __restrict__ bd1,
                                    const float* __restrict__ wd2, const float* __restrict__ bd2,
                                    float* __restrict__ out)
{
    __shared__ float psh[B_SZ * 128];
    __shared__ float hsh[B_SZ * 128];
    const int tid = threadIdx.x;                   // 1024 threads
    psh[tid] = g_pooled[tid];
    __syncthreads();
    const int b = tid >> 7, j = tid & 127;
    float acc = bd1[j];
    const float* wr = wd1 + j * 128;
#pragma unroll 8
    for (int o = 0; o < 128; o++) acc += psh[b * 128 + o] * wr[o];
    hsh[tid] = fmaxf(acc, 0.0f);
    __syncthreads();
    if (tid < B_SZ) {
        float a2 = bd2[0];
#pragma unroll 8
        for (int jj = 0; jj < 128; jj++) a2 += hsh[tid * 128 + jj] * wd2[jj];
        out[tid] = 1.0f / (1.0f + __expf(-a2));
    }
}

// ---------------- launch ----------------
extern "C" void kernel_launch(void* const* d_in, const int* in_sizes, int n_in,
                              void* d_out, int out_size) {
    (void)in_sizes; (void)n_in; (void)out_size;
    const int*   x   = (const int*)d_in[0];
    const float* emb = (const float*)d_in[1];
    const float* w1  = (const float*)d_in[2];
    const float* b1  = (const float*)d_in[3];
    const float* w2  = (const float*)d_in[4];
    const float* b2  = (const float*)d_in[5];
    const float* wd1 = (const float*)d_in[6];
    const float* bd1 = (const float*)d_in[7];
    const float* wd2 = (const float*)d_in[8];
    const float* bd2 = (const float*)d_in[9];
    float* out = (float*)d_out;

    cudaFuncSetAttribute(malconv_main_kernel,
                         cudaFuncAttributeMaxDynamicSharedMemorySize, (int)SMEM_ALLOC);

    malconv_prep_kernel<<<4001, 256>>>(w1, w2, emb);
    malconv_main_kernel<<<GRID_MAIN, 256, SMEM_ALLOC>>>(x, b1, b2);
    malconv_head_kernel<<<1, 1024>>>(wd1, bd1, wd2, bd2, out);
}

// round 9
// speedup vs baseline: 2.8166x; 1.1147x over previous
#include <cuda_runtime.h>
#include <cuda_fp16.h>
#include <cuda_pipeline.h>
#include <cstdint>

// ---------------- problem constants ----------------
#define B_SZ        8
#define L_SZ        1048576
#define KWIN        500
#define T_WIN       2097            // (L-K)/K + 1
#define TILES_PER_B 17              // ceil(2097/128)
#define GRID_MAIN   (B_SZ * TILES_PER_B)   // 136
#define NCHUNK      125             // 500 positions / 4 per chunk (K-chunk = 32)
#define OUT_DESCALE (1.0f / 16384.0f)  // C holds scaled products: 2^14 x true

// 2-term compensated fp16: C = Ah*R + P*Q
//   R = fl16(31/32 * B), rB = 31/32*B - R, Q = fl16(B/32 + rB)
//   Ah = fl16(A),        P  = fl16(Ah + 32*(A - Ah))
// => A-coefficient of B is exact; corrections enter at 2^-16 operand-equiv.

// smem byte offsets
#define OFF_EMBH   0u               // 257 * uint4 (fp16 Ah pairs)
#define OFF_EMBP   4112u            // 257 * uint4 (fp16 P pairs)
#define OFF_BUF    8224u
#define SZ_AH      8192u            // [2 steps][8 mt][32 lanes][4 regs] u32 (lane-swizzled)
#define SZ_AP      8192u
#define SZ_BR      16384u           // [2 steps][32 nt][32 lanes][2 regs] u32
#define SZ_BQ      16384u
#define BUF_SZ     (SZ_AH + SZ_AP + SZ_BR + SZ_BQ)   // 49152
#define OFF_AH(s)  (OFF_BUF + (s)*BUF_SZ)
#define OFF_AP(s)  (OFF_AH(s) + SZ_AH)
#define OFF_BR(s)  (OFF_AP(s) + SZ_AP)
#define OFF_BQ(s)  (OFF_BR(s) + SZ_BR)
#define OFF_GAT    OFF_BUF          // epilogue scratch 128*260*4 = 133120
#define SMEM_ALLOC (OFF_BUF + 128u * 260u * 4u)   // 141344

// ---------------- persistent device scratch ----------------
__device__ __align__(16) unsigned g_br[125 * 4096];   // R frags, k16 frag order per chunk
__device__ __align__(16) unsigned g_bq[125 * 4096];   // Q frags, k16 frag order per chunk
__device__ __align__(16) uint4 g_embh[257];           // Ah pairs e01,e23,e45,e67
__device__ __align__(16) uint4 g_embp[257];           // P  pairs
__device__ float g_pooled[B_SZ * 128];

// ---------------- helpers ----------------
__device__ __forceinline__ float wval(const float* w1, const float* w2, int o, int k) {
    const int kp = k >> 3, e = k & 7;
    const float* w = (o < 128) ? w1 : w2;
    return w[(o & 127) * 4000 + e * 500 + kp] * 128.0f;   // pre-scaled by 2^7
}
__device__ __forceinline__ unsigned pack_h2(float a, float b) {
    __half h0 = __float2half_rn(a), h1 = __float2half_rn(b);
    return ((unsigned)__half_as_ushort(h1) << 16) | __half_as_ushort(h0);
}
__device__ __forceinline__ float bRval(float v) {          // fl16(31/32 v) as float
    return __half2float(__float2half_rn(v * 0.96875f));
}
__device__ __forceinline__ float bQval(float v) {          // B/32 + residual of R
    const float rB = v * 0.96875f - bRval(v);
    return v * 0.03125f + rB;                              // rounded once in pack_h2
}
__device__ __forceinline__ void hmma16816(float* c, uint4 a, uint2 b) {
    asm volatile("mma.sync.aligned.m16n8k16.row.col.f32.f16.f16.f32 "
        "{%0,%1,%2,%3}, {%4,%5,%6,%7}, {%8,%9}, {%0,%1,%2,%3};"
        : "+f"(c[0]), "+f"(c[1]), "+f"(c[2]), "+f"(c[3])
        : "r"(a.x), "r"(a.y), "r"(a.z), "r"(a.w), "r"(b.x), "r"(b.y));
}

// ---------------- prep: fragment-order operand factories ----------------
__global__ void malconv_prep_kernel(const float* __restrict__ w1, const float* __restrict__ w2,
                                    const float* __restrict__ emb)
{
    const int bid = blockIdx.x, tid = threadIdx.x;
    if (bid < 4000) {                                   // BR/BQ: 512000 u32 each, k16 frag order
        const bool isR = bid < 2000;
        const int u = (isR ? bid : bid - 2000) * 256 + tid;
        const int reg = u & 1, lane = (u >> 1) & 31, nt = (u >> 6) & 31;
        const int step = (u >> 11) & 1, ch = u >> 12;
        const int g = lane >> 2, t = lane & 3;
        const int o = nt * 8 + g;
        const int k0 = ch * 32 + step * 16 + reg * 8 + t * 2;
        const float v0 = wval(w1, w2, o, k0), v1 = wval(w1, w2, o, k0 + 1);
        if (isR) g_br[u] = pack_h2(bRval(v0), bRval(v1));
        else     g_bq[u] = pack_h2(bQval(v0), bQval(v1));
    } else {                                            // emb tables + pooled zero
        for (int v = tid; v < 257; v += 256) {
            float a[8], ah[8], p[8];
            unsigned hp[4], pp[4];
#pragma unroll
            for (int e = 0; e < 8; e++) {
                a[e]  = emb[v * 8 + e] * 128.0f;
                ah[e] = __half2float(__float2half_rn(a[e]));
                p[e]  = ah[e] + 32.0f * (a[e] - ah[e]);
            }
#pragma unroll
            for (int q = 0; q < 4; q++) {
                hp[q] = pack_h2(ah[2 * q], ah[2 * q + 1]);
                pp[q] = pack_h2(p[2 * q],  p[2 * q + 1]);
            }
            g_embh[v] = make_uint4(hp[0], hp[1], hp[2], hp[3]);
            g_embp[v] = make_uint4(pp[0], pp[1], pp[2], pp[3]);
        }
        for (int i = tid; i < B_SZ * 128; i += 256) g_pooled[i] = 0.0f;
    }
}

// ---------------- main fused conv GEMM + gate + maxpool ----------------
__global__ void __launch_bounds__(256, 1)
malconv_main_kernel(const int* __restrict__ x,
                    const float* __restrict__ b1, const float* __restrict__ b2)
{
    extern __shared__ __align__(16) char sb[];
    const int tid  = threadIdx.x;
    const int lane = tid & 31;
    const int wid  = tid >> 5;

    const int bidx = blockIdx.x / TILES_PER_B;
    const int tt   = blockIdx.x % TILES_PER_B;
    const int t0   = tt * 128;

    // tables -> smem
    uint4* embh = (uint4*)(sb + OFF_EMBH);
    uint4* embp = (uint4*)(sb + OFF_EMBP);
    for (int i = tid; i < 257; i += 256) { embh[i] = g_embh[i]; embp[i] = g_embp[i]; }

    // A-fill role: 2 threads per row (h = 0/1), 2 conv positions each (p = 2h, 2h+1)
    const int arow = tid >> 1, h = tid & 1;
    int trow = t0 + arow; if (trow >= T_WIN) trow = T_WIN - 1;
    const int* xrow = x + (size_t)bidx * L_SZ + (size_t)trow * KWIN + 2 * h;

    const int mtile = arow >> 4;
    const int g     = arow & 15;
    const int glow  = g & 7, ghi = g >> 3;
    const int so    = glow >> 1;                 // store-side lane swizzle (2 bits)

    // A-fill lambda: writes chunk data for this thread into buffer `buf`,
    // lane-swizzled (logical lane L lives at physical lane L ^ ((L>>3)&3)).
    auto fill_A = [&](int buf, int2 xc) {
        unsigned* AHp = (unsigned*)(sb + OFF_AH(buf));
        unsigned* APp = (unsigned*)(sb + OFF_AP(buf));
#pragma unroll
        for (int i = 0; i < 2; i++) {
            const int v = i ? xc.y : xc.x;
            const uint4 eh = embh[v];
            const uint4 ep = embp[v];
            const int base = ((h * 8 + mtile) * 32 + glow * 4) * 4 + (ghi + 2 * i);
            AHp[base + 4 * (0 ^ so)] = eh.x;
            AHp[base + 4 * (1 ^ so)] = eh.y;
            AHp[base + 4 * (2 ^ so)] = eh.z;
            AHp[base + 4 * (3 ^ so)] = eh.w;
            APp[base + 4 * (0 ^ so)] = ep.x;
            APp[base + 4 * (1 ^ so)] = ep.y;
            APp[base + 4 * (2 ^ so)] = ep.z;
            APp[base + 4 * (3 ^ so)] = ep.w;
        }
    };

    // prologue: cp.async B chunk 0 into buf 0 (BR 1024 quads, BQ 1024 quads)
#pragma unroll
    for (int i = 0; i < 8; i++) {
        if (i < 4) {
            const int q = tid + i * 256;
            __pipeline_memcpy_async(sb + OFF_BR(0) + q * 16, g_br + q * 4, 16);
        } else {
            const int q = tid + (i - 4) * 256;
            __pipeline_memcpy_async(sb + OFF_BQ(0) + q * 16, g_bq + q * 4, 16);
        }
    }
    __pipeline_commit();
    int2 xv = *(const int2*)xrow;                // chunk 0 x-values
    __syncthreads();                             // emb tables ready

    fill_A(0, xv);                               // A(0)
    xv = *(const int2*)(xrow + 4);               // chunk 1 x-values
    __pipeline_wait_prior(0);
    __syncthreads();                             // A(0) + B(0) ready

    // warp tiling: 8 warps = 2(M) x 4(N); warp tile 64x64
    const int wn = wid & 3, wm = wid >> 2;
    const int sl = lane ^ ((lane >> 3) & 3);     // load-side swizzled lane
    float acc[4][8][4];
#pragma unroll
    for (int a = 0; a < 4; a++)
#pragma unroll
        for (int b = 0; b < 8; b++)
#pragma unroll
            for (int j = 0; j < 4; j++) acc[a][b][j] = 0.0f;

    for (int c = 0; c < NCHUNK; ++c) {
        const int s = c & 1;

        // ---- concurrent with MMA(c): fill A(c+1), launch B(c+1) ----
        if (c + 1 < NCHUNK) {
            fill_A(s ^ 1, xv);
            if (c + 2 < NCHUNK) xv = *(const int2*)(xrow + (c + 2) * 4);
            const int ns = s ^ 1;
            const unsigned* br = g_br + (size_t)(c + 1) * 4096;
            const unsigned* bq = g_bq + (size_t)(c + 1) * 4096;
#pragma unroll
            for (int i = 0; i < 8; i++) {
                if (i < 4) {
                    const int q = tid + i * 256;
                    __pipeline_memcpy_async(sb + OFF_BR(ns) + q * 16, br + q * 4, 16);
                } else {
                    const int q = tid + (i - 4) * 256;
                    __pipeline_memcpy_async(sb + OFF_BQ(ns) + q * 16, bq + q * 4, 16);
                }
            }
            __pipeline_commit();
        }

        // ---- MMA on chunk c: 4 HMMA per 16x8 subtile (2 main + 2 correction) ----
        const unsigned* AHp = (const unsigned*)(sb + OFF_AH(s));
        const unsigned* APp = (const unsigned*)(sb + OFF_AP(s));
        const unsigned* BRp = (const unsigned*)(sb + OFF_BR(s));
        const unsigned* BQp = (const unsigned*)(sb + OFF_BQ(s));
#pragma unroll
        for (int mt = 0; mt < 4; mt++) {
            const int MT = wm * 4 + mt;
            const uint4 ah0 = *(const uint4*)(AHp + ((0 + MT) * 32 + sl) * 4);
            const uint4 ah1 = *(const uint4*)(AHp + ((8 + MT) * 32 + sl) * 4);
            const uint4 ap0 = *(const uint4*)(APp + ((0 + MT) * 32 + sl) * 4);
            const uint4 ap1 = *(const uint4*)(APp + ((8 + MT) * 32 + sl) * 4);
#pragma unroll
            for (int nt = 0; nt < 8; nt++) {
                const int NT = wn * 8 + nt;
                const uint2 br0 = *(const uint2*)(BRp + ((0  + NT) * 32 + lane) * 2);
                const uint2 br1 = *(const uint2*)(BRp + ((32 + NT) * 32 + lane) * 2);
                const uint2 bq0 = *(const uint2*)(BQp + ((0  + NT) * 32 + lane) * 2);
                const uint2 bq1 = *(const uint2*)(BQp + ((32 + NT) * 32 + lane) * 2);
                float* C = acc[mt][nt];
                hmma16816(C, ah0, br0);      // Ah * R   (k steps 0,1)
                hmma16816(C, ah1, br1);
                hmma16816(C, ap0, bq0);      // P * Q
                hmma16816(C, ap1, bq1);
            }
        }

        if (c + 1 < NCHUNK) __pipeline_wait_prior(0);
        __syncthreads();                         // next-chunk bufs ready
    }

    // ---- epilogue ----
    float* gat = (float*)(sb + OFF_GAT);                 // [row][o], stride 260
    const int grp = lane >> 2, tig = lane & 3;
#pragma unroll
    for (int mt = 0; mt < 4; mt++)
#pragma unroll
        for (int nt = 0; nt < 8; nt++)
#pragma unroll
            for (int j = 0; j < 4; j++) {
                const int row = wm * 64 + mt * 16 + grp + 8 * (j >> 1);
                const int col = wn * 64 + nt * 8 + 2 * tig + (j & 1);
                gat[row * 260 + col] = acc[mt][nt][j];
            }
    __syncthreads();

    {
        const int o = tid & 127;
        const int half = tid >> 7;
        const float b1v = b1[o], b2v = b2[o];
        int rend = T_WIN - t0; if (rend > 128) rend = 128;
        const int r0 = half * 64;
        int r1 = r0 + 64; if (r1 > rend) r1 = rend;
        float m = 0.0f;
        for (int r = r0; r < r1; r++) {
            const float c1 = gat[r * 260 + o]       * OUT_DESCALE + b1v;
            const float c2 = gat[r * 260 + o + 128] * OUT_DESCALE + b2v;
            const float gg = fmaxf(c1, 0.0f) * (1.0f / (1.0f + __expf(-c2)));
            m = fmaxf(m, gg);
        }
        atomicMax((int*)(g_pooled + bidx * 128 + o), __float_as_int(m));  // m >= 0
    }
}

// ---------------- dense head ----------------
__global__ void malconv_head_kernel(const float* __restrict__ wd1, const float* __restrict__ bd1,
                                    const float* __restrict__ wd2, const float* __restrict__ bd2,
                                    float* __restrict__ out)
{
    __shared__ float psh[B_SZ * 128];
    __shared__ float hsh[B_SZ * 128];
    const int tid = threadIdx.x;                   // 1024 threads
    psh[tid] = g_pooled[tid];
    __syncthreads();
    const int b = tid >> 7, j = tid & 127;
    float acc = bd1[j];
    const float* wr = wd1 + j * 128;
#pragma unroll 8
    for (int o = 0; o < 128; o++) acc += psh[b * 128 + o] * wr[o];
    hsh[tid] = fmaxf(acc, 0.0f);
    __syncthreads();
    if (tid < B_SZ) {
        float a2 = bd2[0];
#pragma unroll 8
        for (int jj = 0; jj < 128; jj++) a2 += hsh[tid * 128 + jj] * wd2[jj];
        out[tid] = 1.0f / (1.0f + __expf(-a2));
    }
}

// ---------------- launch ----------------
extern "C" void kernel_launch(void* const* d_in, const int* in_sizes, int n_in,
                              void* d_out, int out_size) {
    (void)in_sizes; (void)n_in; (void)out_size;
    const int*   x   = (const int*)d_in[0];
    const float* emb = (const float*)d_in[1];
    const float* w1  = (const float*)d_in[2];
    const float* b1  = (const float*)d_in[3];
    const float* w2  = (const float*)d_in[4];
    const float* b2  = (const float*)d_in[5];
    const float* wd1 = (const float*)d_in[6];
    const float* bd1 = (const float*)d_in[7];
    const float* wd2 = (const float*)d_in[8];
    const float* bd2 = (const float*)d_in[9];
    float* out = (float*)d_out;

    cudaFuncSetAttribute(malconv_main_kernel,
                         cudaFuncAttributeMaxDynamicSharedMemorySize, (int)SMEM_ALLOC);

    malconv_prep_kernel<<<4001, 256>>>(w1, w2, emb);
    malconv_main_kernel<<<GRID_MAIN, 256, SMEM_ALLOC>>>(x, b1, b2);
    malconv_head_kernel<<<1, 1024>>>(wd1, bd1, wd2, bd2, out);
}